// round 11
// baseline (speedup 1.0000x reference)
#include <cuda_runtime.h>
#include <math.h>

#define BB 8
#define H 256
#define W 256
#define NPIX (H*W)
#define GRID 512
#define PREP_BLOCKS 64
#define NGRP 64                          // 8 blocks per group, 8 groups per image
#define LUTN 1024

// Scratch (device globals — no allocation allowed)
__device__ unsigned int g_cm[BB*W*8];    // column seed masks: [(b*W+j)*8 + slab]
__device__ float  g_pd[GRID];            // per-block sum(pred*d)
__device__ float  g_d [GRID];            // per-block sum(d)
__device__ float  g_mx[GRID];            // per-block max(d)
__device__ double g_gd[NGRP], g_gp[NGRP];// per-group sums
__device__ float  g_gm[NGRP];            // per-group max
__device__ unsigned int g_barA[BB] = {}; // per-image phase-A arrival counters
__device__ unsigned int g_t1[NGRP] = {}; // per-group completion counters
__device__ unsigned int g_t2 = 0;        // group-level completion counter

union SmemU {
    struct {                             // phase A
        unsigned int tb[H];
        unsigned int hm[H];
        unsigned int bd[H];
    } a;
    struct {                             // phase B: 4 rows, each padded [W|W|W]
        float s[4][3*W];
    } b;
};

__device__ __forceinline__ float fast_sigmoid(float x) {
    float th;
    asm("tanh.approx.f32 %0, %1;" : "=f"(th) : "f"(x * 0.5f));
    return fmaf(0.5f, th, 0.5f);
}

__global__ void __launch_bounds__(256, 4)
k_fused(const float* __restrict__ logits, const int* __restrict__ target,
        float* __restrict__ out) {
    __shared__ SmemU u;
    __shared__ float s_lut[LUTN];
    __shared__ float rs[8], rp[8], rm[8];
    __shared__ bool sLastG, sLastAll;

    int bid = blockIdx.x;
    int tid = threadIdx.x;
    int w = tid >> 5, lane = tid & 31;

    // ====== Prefetch logits (independent; hides DRAM latency) ===============
    int pb = bid >> 6;                   // phase-B image
    int i0 = (bid & 63) * 4;             // phase-B first row (same 32-row slab)
    int j = tid;                         // phase-B column
    float xl[4];
    #pragma unroll
    for (int r = 0; r < 4; r++)
        xl[r] = logits[(pb * H + i0 + r) * W + j];

    // ====== Phase A (blocks 0..63): (image, 32-col group) full stripe =======
    if (bid < PREP_BLOCKS) {
        int b = bid >> 3;
        int g = bid & 7;
        const int* t = target + b * NPIX;
        int colbase = g << 5;

        // halo ballots: lane -> row (w<<5)+lane
        unsigned int lm, rmm;
        {
            int i = (w << 5) + lane;
            int Lv = (g > 0) ? t[i * W + colbase - 1]  : 0;
            int Rv = (g < 7) ? t[i * W + colbase + 32] : 0;
            lm  = __ballot_sync(0xffffffffu, Lv != 0);
            rmm = __ballot_sync(0xffffffffu, Rv != 0);
        }

        // pack + horizontal 3-AND fused; batch 16 loads -> 16 ballots
        #pragma unroll
        for (int batch = 0; batch < 2; batch++) {
            int v[16];
            #pragma unroll
            for (int r = 0; r < 16; r++) {
                int i = (w << 5) + batch * 16 + r;
                v[r] = t[i * W + colbase + lane];
            }
            #pragma unroll
            for (int r = 0; r < 16; r++) {
                int rr = batch * 16 + r;
                unsigned int m = __ballot_sync(0xffffffffu, v[r] != 0);
                unsigned int Lb = (lm  >> rr) & 1u;
                unsigned int Rb = (rmm >> rr) & 1u;
                unsigned int hmv = m & ((m << 1) | Lb) & ((m >> 1) | (Rb << 31));
                if (lane == 0) {
                    u.a.tb[(w << 5) + rr] = m;
                    u.a.hm[(w << 5) + rr] = hmv;
                }
            }
        }
        __syncthreads();                                 // (1)

        // erosion per row (read-only on tb/hm, write bd: no hazard)
        {
            int i = tid;
            unsigned int er = (i > 0 && i < H - 1)
                            ? (u.a.hm[i - 1] & u.a.hm[i] & u.a.hm[i + 1]) : 0u;
            if (g == 0) er &= ~1u;
            if (g == 7) er &= ~(1u << 31);
            u.a.bd[i] = u.a.tb[i] ^ er;
        }
        __syncthreads();                                 // (2)

        // 32x32 bit transpose per warp; lane j gets column j's slab bits
        unsigned int word = u.a.bd[(w << 5) + lane];
        unsigned int v = 0u;
        #pragma unroll
        for (int jj = 0; jj < 32; jj++) {
            unsigned int bm = __ballot_sync(0xffffffffu, (word >> jj) & 1u);
            if (lane == jj) v = bm;
        }
        g_cm[((b * W) + colbase + lane) * 8 + w] = v;

        __threadfence();
        __syncthreads();                                 // (3)
        if (tid == 0) atomicAdd(&g_barA[b], 1u);
    }

    // ====== Pre-barrier work with no phase-A dependency =====================
    // sqrt LUT computed locally (m is an exact small integer; values identical
    // to sqrtf of before). 4 MUFU ops per thread.
    #pragma unroll
    for (int k = 0; k < 4; k++) {
        int idx = tid + k * 256;
        s_lut[idx] = sqrtf((float)idx);
    }
    #pragma unroll
    for (int r = 0; r < 4; r++) {
        u.b.s[r][j] = 1e30f;             // left pad
        u.b.s[r][2 * W + j] = 1e30f;     // right pad
    }

    // ====== Per-image barrier (only this image's 8 prep blocks) =============
    if (tid == 0) {
        while (*(volatile unsigned int*)&g_barA[pb] < 8) __nanosleep(32);
    }
    __syncthreads();

    // ====== Phase B: vertical distance from bitmask + exact min-plus ========
    const uint4* cmp = (const uint4*)&g_cm[((pb * W) + j) * 8];
    uint4 lov = cmp[0], hiv = cmp[1];
    unsigned int cm[8] = {lov.x, lov.y, lov.z, lov.w, hiv.x, hiv.y, hiv.z, hiv.w};

    int ws = i0 >> 5;
    int P = -1000000, N = 1000000;
    #pragma unroll
    for (int k = 0; k < 8; k++) {
        if (k < ws && cm[k]) P = (k << 5) + 31 - __clz(cm[k]);
        if (k > ws && cm[k] && N == 1000000) N = (k << 5) + __ffs(cm[k]) - 1;
    }
    unsigned int vw = cm[ws];

    #pragma unroll
    for (int r = 0; r < 4; r++) {
        int i = i0 + r, bi = i & 31;
        unsigned int below = vw & (0xFFFFFFFFu >> (31 - bi));
        unsigned int above = vw & (0xFFFFFFFFu << bi);
        int last = below ? ((ws << 5) + 31 - __clz(below)) : P;
        int nxt  = above ? ((ws << 5) + __ffs(above) - 1)  : N;
        int f = min(min(i - last, nxt - i), 10000);      // BIG clip (1e4)
        u.b.s[r][W + j] = (float)(f * f);                // exact in fp32
    }
    __syncthreads();

    // exact min-plus per pixel, per-lane early exit; d via smem LUT
    float sd = 0.f, sp = 0.f, mxv = 0.f;
    #pragma unroll
    for (int r = 0; r < 4; r++) {
        const float* s = u.b.s[r];
        float m = s[W + j];
        float fo = 1.f;
        while (fo * fo < m) {
            float o2 = fo * fo;
            int o = (int)fo;
            m = fminf(m, s[W + j - o] + o2);
            m = fminf(m, s[W + j + o] + o2);
            fo += 1.f;
        }
        int mi = (int)m;
        float d = (mi < LUTN) ? s_lut[mi] : sqrtf(m);
        float pred = fast_sigmoid(xl[r]);
        sd += d;
        sp += pred * d;
        mxv = fmaxf(mxv, d);
    }

    // deterministic block reduction -> per-block partials
    #pragma unroll
    for (int o = 16; o; o >>= 1) {
        sd  += __shfl_down_sync(0xffffffffu, sd,  o);
        sp  += __shfl_down_sync(0xffffffffu, sp,  o);
        mxv  = fmaxf(mxv, __shfl_down_sync(0xffffffffu, mxv, o));
    }
    if (lane == 0) { rs[w] = sd; rp[w] = sp; rm[w] = mxv; }
    __syncthreads();

    int grp = bid >> 3;                  // 8 blocks per group, same image
    if (tid == 0) {
        float S = 0.f, Pp = 0.f, M = 0.f;
        #pragma unroll
        for (int k = 0; k < 8; k++) { S += rs[k]; Pp += rp[k]; M = fmaxf(M, rm[k]); }
        g_d[bid] = S; g_pd[bid] = Pp; g_mx[bid] = M;
        __threadfence();
        unsigned int tk = atomicAdd(&g_t1[grp], 1u);
        sLastG = (tk == 7u);
    }
    __syncthreads();
    if (!sLastG) return;

    // ====== Group leader: reduce 8 block partials (fixed order, double) =====
    if (tid == 0) {
        int g0 = grp << 3;
        float ld[8], lp[8], lx[8];
        #pragma unroll
        for (int k = 0; k < 8; k++) {    // independent loads (MLP=8)
            ld[k] = g_d [g0 + k];
            lp[k] = g_pd[g0 + k];
            lx[k] = g_mx[g0 + k];
        }
        double gd = 0.0, gp = 0.0; float gm = 0.f;
        #pragma unroll
        for (int k = 0; k < 8; k++) {
            gd += (double)ld[k]; gp += (double)lp[k]; gm = fmaxf(gm, lx[k]);
        }
        g_gd[grp] = gd; g_gp[grp] = gp; g_gm[grp] = gm;
        g_t1[grp] = 0;                   // reset for next graph replay
        __threadfence();
        unsigned int tk2 = atomicAdd(&g_t2, 1u);
        sLastAll = (tk2 == NGRP - 1);
    }
    __syncthreads();
    if (!sLastAll) return;

    // ====== Final block: 8 warps, warp w = image w, lane<8 = group ==========
    {
        double sdd = 0.0, spp = 0.0;
        float mxx = 0.f;
        if (lane < 8) {
            int gg = w * 8 + lane;
            sdd = g_gd[gg]; spp = g_gp[gg]; mxx = g_gm[gg];
        }
        #pragma unroll
        for (int o = 4; o; o >>= 1) {
            sdd += __shfl_down_sync(0xffffffffu, sdd, o);
            spp += __shfl_down_sync(0xffffffffu, spp, o);
            mxx  = fmaxf(mxx, __shfl_down_sync(0xffffffffu, mxx, o));
        }
        __shared__ double sper[BB];
        if (lane == 0)
            sper[w] = spp / (sdd + 1e-7 * ((double)mxx + 1e-7));
        __syncthreads();
        if (tid == 0) {
            double acc = 0.0;
            #pragma unroll
            for (int k = 0; k < BB; k++) acc += sper[k];
            out[0] = (float)(acc / BB);
            g_t2 = 0;                    // reset for next graph replay
            #pragma unroll
            for (int k = 0; k < BB; k++) g_barA[k] = 0;
        }
    }
}

extern "C" void kernel_launch(void* const* d_in, const int* in_sizes, int n_in,
                              void* d_out, int out_size) {
    const float* logits = (const float*)d_in[0];
    const int*   target = (const int*)d_in[1];
    float* out = (float*)d_out;

    k_fused<<<GRID, 256>>>(logits, target, out);
}